// round 3
// baseline (speedup 1.0000x reference)
#include <cuda_runtime.h>
#include <math.h>

#define NROWS 32768
#define KDIM  1024

// ---------------- device scratch (no allocations allowed) ----------------
__device__ alignas(16) float g_gates[4096];
__device__ alignas(16) float g_h[2048];
__device__ alignas(16) float g_c[2048];
__device__ alignas(16) float g_zconst[1024];
__device__ alignas(16) float g_context[1024];
__device__ alignas(16) float g_wenc[1024];
__device__ alignas(16) float g_logits[NROWS];
__device__ alignas(16) float g_attn[NROWS];
__device__ alignas(16) float g_colpart[64 * 1024];

// ---------------- f32x2 packed-FMA helpers (Blackwell FFMA2) ----------------
__device__ __forceinline__ unsigned long long f32x2_dup(float b) {
    unsigned long long r;
    unsigned u = __float_as_uint(b);
    asm("mov.b64 %0, {%1, %2};" : "=l"(r) : "r"(u), "r"(u));
    return r;
}
__device__ __forceinline__ void f32x2_fma(unsigned long long& d,
                                          unsigned long long a,
                                          unsigned long long b) {
    asm("fma.rn.f32x2 %0, %1, %2, %3;" : "=l"(d) : "l"(a), "l"(b), "l"(d));
}
__device__ __forceinline__ float2 f32x2_unpack(unsigned long long v) {
    unsigned lo, hi;
    asm("mov.b64 {%0, %1}, %2;" : "=r"(lo), "=r"(hi) : "l"(v));
    return make_float2(__uint_as_float(lo), __uint_as_float(hi));
}

__device__ __forceinline__ float sigmoidf_(float x) { return 1.f / (1.f + expf(-x)); }

// ---------------- LSTM ----------------
// gates[r] = dot(W_ih[r], x) + dot(W_hh[r], h_prev) + b_ih[r] + b_hh[r], r in [0,4096)
__global__ void lstm_gates_kernel(const float* __restrict__ Wih,
                                  const float* __restrict__ Whh,
                                  const float* __restrict__ bih,
                                  const float* __restrict__ bhh,
                                  const float* x_in,
                                  const float* __restrict__ hprev) {
    int gw = (blockIdx.x * 256 + threadIdx.x) >> 5;  // 0..4095
    int lane = threadIdx.x & 31;
    const float* x = x_in ? x_in : g_h;  // layer 1 input = layer 0 h
    const float4* wi = (const float4*)(Wih + (size_t)gw * KDIM);
    const float4* wh = (const float4*)(Whh + (size_t)gw * KDIM);
    const float4* x4 = (const float4*)x;
    const float4* h4 = (const float4*)hprev;
    float s = 0.f;
#pragma unroll
    for (int i = 0; i < 8; ++i) {
        float4 a = wi[lane + i * 32], b = x4[lane + i * 32];
        s = fmaf(a.x, b.x, fmaf(a.y, b.y, fmaf(a.z, b.z, fmaf(a.w, b.w, s))));
        float4 c2 = wh[lane + i * 32], d2 = h4[lane + i * 32];
        s = fmaf(c2.x, d2.x, fmaf(c2.y, d2.y, fmaf(c2.z, d2.z, fmaf(c2.w, d2.w, s))));
    }
#pragma unroll
    for (int o = 16; o; o >>= 1) s += __shfl_xor_sync(0xffffffffu, s, o);
    if (lane == 0) g_gates[gw] = s + bih[gw] + bhh[gw];
}

__global__ void lstm_combine_kernel(const float* __restrict__ c_prev, int layer) {
    int j = threadIdx.x;  // 1024 threads
    float gi = g_gates[j];
    float gf = g_gates[1024 + j];
    float gg = g_gates[2048 + j];
    float go = g_gates[3072 + j];
    float c = sigmoidf_(gf) * c_prev[j] + sigmoidf_(gi) * tanhf(gg);
    float h = sigmoidf_(go) * tanhf(c);
    g_c[layer * 1024 + j] = c;
    g_h[layer * 1024 + j] = h;
}

// ---------------- generic 1024x1024 matvec ----------------
// x_sel: 1 -> g_h+1024 (lstm output), 2 -> g_wenc, 3 -> g_context
// out_sel: 0 -> g_zconst, 1 -> g_context
__global__ void matvec_kernel(const float* __restrict__ W,
                              const float* __restrict__ b0,
                              const float* __restrict__ b1,
                              const float* __restrict__ b2,
                              int x_sel, int out_sel) {
    int gw = (blockIdx.x * 256 + threadIdx.x) >> 5;  // 0..1023
    int lane = threadIdx.x & 31;
    const float* x = (x_sel == 1) ? (g_h + 1024) : (x_sel == 2 ? g_wenc : g_context);
    const float4* wr = (const float4*)(W + (size_t)gw * KDIM);
    const float4* x4 = (const float4*)x;
    float s = 0.f;
#pragma unroll
    for (int i = 0; i < 8; ++i) {
        float4 a = wr[lane + i * 32], b = x4[lane + i * 32];
        s = fmaf(a.x, b.x, fmaf(a.y, b.y, fmaf(a.z, b.z, fmaf(a.w, b.w, s))));
    }
#pragma unroll
    for (int o = 16; o; o >>= 1) s += __shfl_xor_sync(0xffffffffu, s, o);
    if (lane == 0) {
        if (b0) s += b0[gw];
        if (b1) s += b1[gw];
        if (b2) s += b2[gw];
        if (out_sel == 0) g_zconst[gw] = s;
        else              g_context[gw] = s;
    }
}

// ---------------- fused score GEMM ----------------
// logits[n] = sum_j v[j] * tanh( (A @ W^T)[n,j] + zconst[j] + cov[n]*wc[j] )
// A: [N,1024] row-major, W: [1024,1024] row-major (K contiguous for both).
#define BM 128
#define BN 128
#define BK 16
#define NKT (KDIM / BK)  // 64
#define NJT (KDIM / BN)  // 8

__global__ __launch_bounds__(256, 1)
void score_gemm_kernel(const float* __restrict__ A, const float* __restrict__ W,
                       const float* __restrict__ cov, const float* __restrict__ wc,
                       const float* __restrict__ vvec) {
    __shared__ alignas(16) float As[BK][BM];
    __shared__ alignas(16) float Bs[BK][BN];
    __shared__ float red[BM][17];
    __shared__ float rowsum[BM];
    __shared__ float s_cov[BM];
    __shared__ float s_cv[BN], s_wc[BN], s_v[BN];

    const int tid = threadIdx.x;
    const int n0 = blockIdx.x * BM;
    const int tx = tid & 15;   // col group (8 cols)
    const int ty = tid >> 4;   // row group (8 rows)
    const float4* A4 = (const float4*)A;
    const float4* W4 = (const float4*)W;

    if (tid < BM) {
        rowsum[tid] = 0.f;
        s_cov[tid] = cov[n0 + tid];
    }

    for (int jt = 0; jt < NJT; ++jt) {
        __syncthreads();
        if (tid < BN) {
            int j = jt * BN + tid;
            s_cv[tid] = g_zconst[j];
            s_wc[tid] = wc[j];
            s_v[tid]  = vvec[j];
        }
        unsigned long long acc[4][8];
#pragma unroll
        for (int ii = 0; ii < 4; ++ii)
#pragma unroll
            for (int j = 0; j < 8; ++j) acc[ii][j] = 0ull;

        for (int kt = 0; kt < NKT; ++kt) {
            __syncthreads();
#pragma unroll
            for (int r = 0; r < 2; ++r) {
                int q = tid * 2 + r;            // 0..511
                int row = q >> 2, kq = q & 3;
                float4 va = A4[(size_t)(n0 + row) * (KDIM / 4) + kt * 4 + kq];
                As[kq * 4 + 0][row] = va.x; As[kq * 4 + 1][row] = va.y;
                As[kq * 4 + 2][row] = va.z; As[kq * 4 + 3][row] = va.w;
                float4 vb = W4[(size_t)(jt * BN + row) * (KDIM / 4) + kt * 4 + kq];
                Bs[kq * 4 + 0][row] = vb.x; Bs[kq * 4 + 1][row] = vb.y;
                Bs[kq * 4 + 2][row] = vb.z; Bs[kq * 4 + 3][row] = vb.w;
            }
            __syncthreads();
#pragma unroll
            for (int kk = 0; kk < BK; ++kk) {
                const ulonglong2* pa = (const ulonglong2*)&As[kk][ty * 8];
                ulonglong2 a01 = pa[0], a23 = pa[1];
                unsigned long long a2[4] = {a01.x, a01.y, a23.x, a23.y};
                const float4* pb = (const float4*)&Bs[kk][tx * 8];
                float4 b0 = pb[0], b1 = pb[1];
                unsigned long long bb[8];
                bb[0] = f32x2_dup(b0.x); bb[1] = f32x2_dup(b0.y);
                bb[2] = f32x2_dup(b0.z); bb[3] = f32x2_dup(b0.w);
                bb[4] = f32x2_dup(b1.x); bb[5] = f32x2_dup(b1.y);
                bb[6] = f32x2_dup(b1.z); bb[7] = f32x2_dup(b1.w);
#pragma unroll
                for (int ii = 0; ii < 4; ++ii)
#pragma unroll
                    for (int j = 0; j < 8; ++j)
                        f32x2_fma(acc[ii][j], a2[ii], bb[j]);
            }
        }
        // epilogue: reduce tanh over this 128-col tile into per-row partials
        float rp[8];
#pragma unroll
        for (int i = 0; i < 8; ++i) rp[i] = 0.f;
#pragma unroll
        for (int ii = 0; ii < 4; ++ii) {
            float c0 = s_cov[ty * 8 + 2 * ii];
            float c1 = s_cov[ty * 8 + 2 * ii + 1];
#pragma unroll
            for (int j = 0; j < 8; ++j) {
                float2 ch = f32x2_unpack(acc[ii][j]);
                int jc = tx * 8 + j;
                float base = s_cv[jc];
                float w    = s_wc[jc];
                float vv   = s_v[jc];
                rp[2 * ii]     += vv * tanhf(ch.x + base + c0 * w);
                rp[2 * ii + 1] += vv * tanhf(ch.y + base + c1 * w);
            }
        }
#pragma unroll
        for (int i = 0; i < 8; ++i) red[ty * 8 + i][tx] = rp[i];
        __syncthreads();
        if (tid < BM) {
            float s = 0.f;
#pragma unroll
            for (int t = 0; t < 16; ++t) s += red[tid][t];
            rowsum[tid] += s;
        }
    }
    __syncthreads();
    if (tid < BM) g_logits[n0 + tid] = rowsum[tid];
}

// ---------------- softmax (single CTA, deterministic) ----------------
// logit = g_logits[n] + vb; optional relu; prob = softmax; cov_out = cov + prob
__global__ void softmax_kernel(const float* __restrict__ vbp,
                               const float* __restrict__ cov,
                               float* __restrict__ prob_ext,
                               float* __restrict__ cov_out,
                               int do_relu) {
    __shared__ float shred[32];
    __shared__ float bval;
    int tid = threadIdx.x;  // 1024
    float vb = vbp[0];
    float lmax = -3.4e38f;
    for (int n = tid; n < NROWS; n += 1024) {
        float l = g_logits[n] + vb;
        if (do_relu) l = fmaxf(l, 0.f);
        g_logits[n] = l;
        lmax = fmaxf(lmax, l);
    }
#pragma unroll
    for (int o = 16; o; o >>= 1) lmax = fmaxf(lmax, __shfl_xor_sync(0xffffffffu, lmax, o));
    if ((tid & 31) == 0) shred[tid >> 5] = lmax;
    __syncthreads();
    if (tid < 32) {
        float v = shred[tid];
#pragma unroll
        for (int o = 16; o; o >>= 1) v = fmaxf(v, __shfl_xor_sync(0xffffffffu, v, o));
        if (tid == 0) bval = v;
    }
    __syncthreads();
    float m = bval;
    float lsum = 0.f;
    for (int n = tid; n < NROWS; n += 1024) lsum += expf(g_logits[n] - m);
#pragma unroll
    for (int o = 16; o; o >>= 1) lsum += __shfl_xor_sync(0xffffffffu, lsum, o);
    __syncthreads();
    if ((tid & 31) == 0) shred[tid >> 5] = lsum;
    __syncthreads();
    if (tid < 32) {
        float v = shred[tid];
#pragma unroll
        for (int o = 16; o; o >>= 1) v += __shfl_xor_sync(0xffffffffu, v, o);
        if (tid == 0) bval = v;
    }
    __syncthreads();
    float inv = 1.f / bval;
    float* prob = prob_ext ? prob_ext : g_attn;
    for (int n = tid; n < NROWS; n += 1024) {
        float p = expf(g_logits[n] - m) * inv;
        prob[n] = p;
        if (cov_out) cov_out[n] = cov[n] + p;
    }
}

// ---------------- weighted column sum: g_wenc = enc^T @ attn ----------------
__global__ void wsum_partial_kernel(const float* __restrict__ enc) {
    int col = blockIdx.x * 256 + threadIdx.x;  // gridDim.x = 4
    int n0 = blockIdx.y * 512;                 // gridDim.y = 64
    float s = 0.f;
#pragma unroll 4
    for (int n = n0; n < n0 + 512; ++n)
        s = fmaf(g_attn[n], enc[(size_t)n * KDIM + col], s);
    g_colpart[blockIdx.y * KDIM + col] = s;
}
__global__ void wsum_reduce_kernel() {
    int col = threadIdx.x;  // 1024
    float s = 0.f;
#pragma unroll
    for (int i = 0; i < 64; ++i) s += g_colpart[i * KDIM + col];
    g_wenc[col] = s;
}

// ---------------- h/c output copy ----------------
__global__ void copy_hc_kernel(float* __restrict__ oh, float* __restrict__ oc) {
    int i = blockIdx.x * blockDim.x + threadIdx.x;
    if (i < 2048) {
        oh[i] = g_h[i];
        oc[i] = g_c[i];
    }
}

// ---------------- launch ----------------
extern "C" void kernel_launch(void* const* d_in, const int* in_sizes, int n_in,
                              void* d_out, int out_size) {
    (void)in_sizes; (void)n_in;
    const float* inp   = (const float*)d_in[0];
    const float* h0    = (const float*)d_in[1];
    const float* c0    = (const float*)d_in[2];
    const float* enc   = (const float*)d_in[3];
    const float* cov_g = (const float*)d_in[4];
    const float* cov_p = (const float*)d_in[5];
    const float* Wih   = (const float*)d_in[6];
    const float* Whh   = (const float*)d_in[7];
    const float* bih   = (const float*)d_in[8];
    const float* bhh   = (const float*)d_in[9];
    const float* gw1   = (const float*)d_in[10];
    const float* gb1   = (const float*)d_in[11];
    const float* gw2   = (const float*)d_in[12];
    const float* gb2   = (const float*)d_in[13];
    const float* gwc   = (const float*)d_in[14];
    const float* gbc   = (const float*)d_in[15];
    const float* gv    = (const float*)d_in[16];
    const float* gvb   = (const float*)d_in[17];
    const float* pw1   = (const float*)d_in[18];
    const float* pb1   = (const float*)d_in[19];
    const float* pw2   = (const float*)d_in[20];
    const float* pb2   = (const float*)d_in[21];
    const float* pwc   = (const float*)d_in[22];
    const float* pbc   = (const float*)d_in[23];
    const float* pv    = (const float*)d_in[24];
    const float* pvb   = (const float*)d_in[25];

    float* out = (float*)d_out;
    const int FULL = 32768 + 2048 + 2048 + 32768 + 32768;  // 102400
    bool full = out_size >= FULL;
    float* out_h  = full ? out + 32768 : nullptr;
    float* out_c  = full ? out + 34816 : nullptr;
    float* out_cg = full ? out + 36864 : nullptr;
    float* out_cp = full ? out + 69632 : nullptr;

    // LSTM layer 0 (x = _input, h/c = h0[0]/c0[0])
    lstm_gates_kernel<<<512, 256>>>(Wih, Whh, bih, bhh, inp, h0);
    lstm_combine_kernel<<<1, 1024>>>(c0, 0);
    // LSTM layer 1 (x = g_h[0:1024], h/c = h0[1]/c0[1])
    lstm_gates_kernel<<<512, 256>>>(Wih + (size_t)4096 * 1024, Whh + (size_t)4096 * 1024,
                                    bih + 4096, bhh + 4096, nullptr, h0 + 1024);
    lstm_combine_kernel<<<1, 1024>>>(c0 + 1024, 1);

    // zconst_g = g_w2 @ lstm_out + g_b2 + g_b1 + g_bc
    matvec_kernel<<<128, 256>>>(gw2, gb2, gb1, gbc, /*x_sel=*/1, /*out_sel=*/0);

    // glimpse attention logits (fused GEMM + tanh + v-dot)
    score_gemm_kernel<<<256, 256>>>(enc, gw1, cov_g, gwc, gv);
    // attn = softmax(logits + vb); cov_g_new = cov_g + attn
    softmax_kernel<<<1, 1024>>>(gvb, cov_g, nullptr, out_cg, 0);

    // weighted_enc = enc^T @ attn  (context = g_w1 @ weighted_enc + g_b1)
    wsum_partial_kernel<<<dim3(4, 64), 256>>>(enc);
    wsum_reduce_kernel<<<1, 1024>>>();
    matvec_kernel<<<128, 256>>>(gw1, gb1, nullptr, nullptr, /*x_sel=*/2, /*out_sel=*/1);

    // zconst_p = p_w2 @ context + p_b2 + p_b1 + p_bc
    matvec_kernel<<<128, 256>>>(pw2, pb2, pb1, pbc, /*x_sel=*/3, /*out_sel=*/0);

    // pointer logits
    score_gemm_kernel<<<256, 256>>>(enc, pw1, cov_p, pwc, pv);
    // u = relu(logits + vb); cond_p = softmax(u) -> d_out; cov_p_new = cov_p + cond_p
    softmax_kernel<<<1, 1024>>>(pvb, cov_p, out, out_cp, 1);

    if (full) copy_hc_kernel<<<2, 1024>>>(out_h, out_c);
}

// round 4
// speedup vs baseline: 1.0041x; 1.0041x over previous
#include <cuda_runtime.h>
#include <math.h>

#define NROWS 32768
#define KDIM  1024

// ---------------- device scratch (no allocations allowed) ----------------
__device__ alignas(16) float g_gates[4096];
__device__ alignas(16) float g_h[2048];
__device__ alignas(16) float g_c[2048];
__device__ alignas(16) float g_zconst[1024];
__device__ alignas(16) float g_context[1024];
__device__ alignas(16) float g_wenc[1024];
__device__ alignas(16) float g_logits[NROWS];
__device__ alignas(16) float g_attn[NROWS];
__device__ alignas(16) float g_colpart[64 * 1024];

// ---------------- f32x2 packed-FMA helpers (Blackwell FFMA2) ----------------
__device__ __forceinline__ unsigned long long f32x2_dup(float b) {
    unsigned long long r;
    unsigned u = __float_as_uint(b);
    asm("mov.b64 %0, {%1, %2};" : "=l"(r) : "r"(u), "r"(u));
    return r;
}
__device__ __forceinline__ void f32x2_fma(unsigned long long& d,
                                          unsigned long long a,
                                          unsigned long long b) {
    asm("fma.rn.f32x2 %0, %1, %2, %3;" : "=l"(d) : "l"(a), "l"(b), "l"(d));
}
__device__ __forceinline__ float2 f32x2_unpack(unsigned long long v) {
    unsigned lo, hi;
    asm("mov.b64 {%0, %1}, %2;" : "=r"(lo), "=r"(hi) : "l"(v));
    return make_float2(__uint_as_float(lo), __uint_as_float(hi));
}

__device__ __forceinline__ float sigmoidf_(float x) { return 1.f / (1.f + expf(-x)); }

// ---------------- LSTM ----------------
// gates[r] = dot(W_ih[r], x) + dot(W_hh[r], h_prev) + b_ih[r] + b_hh[r], r in [0,4096)
__global__ void lstm_gates_kernel(const float* __restrict__ Wih,
                                  const float* __restrict__ Whh,
                                  const float* __restrict__ bih,
                                  const float* __restrict__ bhh,
                                  const float* x_in,
                                  const float* __restrict__ hprev) {
    int gw = (blockIdx.x * 256 + threadIdx.x) >> 5;  // 0..4095
    int lane = threadIdx.x & 31;
    const float* x = x_in ? x_in : g_h;  // layer 1 input = layer 0 h
    const float4* wi = (const float4*)(Wih + (size_t)gw * KDIM);
    const float4* wh = (const float4*)(Whh + (size_t)gw * KDIM);
    const float4* x4 = (const float4*)x;
    const float4* h4 = (const float4*)hprev;
    float s = 0.f;
#pragma unroll
    for (int i = 0; i < 8; ++i) {
        float4 a = wi[lane + i * 32], b = x4[lane + i * 32];
        s = fmaf(a.x, b.x, fmaf(a.y, b.y, fmaf(a.z, b.z, fmaf(a.w, b.w, s))));
        float4 c2 = wh[lane + i * 32], d2 = h4[lane + i * 32];
        s = fmaf(c2.x, d2.x, fmaf(c2.y, d2.y, fmaf(c2.z, d2.z, fmaf(c2.w, d2.w, s))));
    }
#pragma unroll
    for (int o = 16; o; o >>= 1) s += __shfl_xor_sync(0xffffffffu, s, o);
    if (lane == 0) g_gates[gw] = s + bih[gw] + bhh[gw];
}

__global__ void lstm_combine_kernel(const float* __restrict__ c_prev, int layer) {
    int j = threadIdx.x;  // 1024 threads
    float gi = g_gates[j];
    float gf = g_gates[1024 + j];
    float gg = g_gates[2048 + j];
    float go = g_gates[3072 + j];
    float c = sigmoidf_(gf) * c_prev[j] + sigmoidf_(gi) * tanhf(gg);
    float h = sigmoidf_(go) * tanhf(c);
    g_c[layer * 1024 + j] = c;
    g_h[layer * 1024 + j] = h;
}

// ---------------- generic 1024x1024 matvec ----------------
// x_sel: 1 -> g_h+1024 (lstm output), 2 -> g_wenc, 3 -> g_context
// out_sel: 0 -> g_zconst, 1 -> g_context
__global__ void matvec_kernel(const float* __restrict__ W,
                              const float* __restrict__ b0,
                              const float* __restrict__ b1,
                              const float* __restrict__ b2,
                              int x_sel, int out_sel) {
    int gw = (blockIdx.x * 256 + threadIdx.x) >> 5;  // 0..1023
    int lane = threadIdx.x & 31;
    const float* x = (x_sel == 1) ? (g_h + 1024) : (x_sel == 2 ? g_wenc : g_context);
    const float4* wr = (const float4*)(W + (size_t)gw * KDIM);
    const float4* x4 = (const float4*)x;
    float s = 0.f;
#pragma unroll
    for (int i = 0; i < 8; ++i) {
        float4 a = wr[lane + i * 32], b = x4[lane + i * 32];
        s = fmaf(a.x, b.x, fmaf(a.y, b.y, fmaf(a.z, b.z, fmaf(a.w, b.w, s))));
    }
#pragma unroll
    for (int o = 16; o; o >>= 1) s += __shfl_xor_sync(0xffffffffu, s, o);
    if (lane == 0) {
        if (b0) s += b0[gw];
        if (b1) s += b1[gw];
        if (b2) s += b2[gw];
        if (out_sel == 0) g_zconst[gw] = s;
        else              g_context[gw] = s;
    }
}

// ---------------- fused score GEMM ----------------
// logits[n] = sum_j v[j] * tanh( (A @ W^T)[n,j] + zconst[j] + cov[n]*wc[j] )
// A: [N,1024] row-major, W: [1024,1024] row-major (K contiguous for both).
#define BM 128
#define BN 128
#define BK 16
#define NKT (KDIM / BK)  // 64
#define NJT (KDIM / BN)  // 8

__global__ __launch_bounds__(256, 1)
void score_gemm_kernel(const float* __restrict__ A, const float* __restrict__ W,
                       const float* __restrict__ cov, const float* __restrict__ wc,
                       const float* __restrict__ vvec) {
    __shared__ alignas(16) float As[BK][BM];
    __shared__ alignas(16) float Bs[BK][BN];
    __shared__ float red[BM][17];
    __shared__ float rowsum[BM];
    __shared__ float s_cov[BM];
    __shared__ float s_cv[BN], s_wc[BN], s_v[BN];

    const int tid = threadIdx.x;
    const int n0 = blockIdx.x * BM;
    const int tx = tid & 15;   // col group (8 cols)
    const int ty = tid >> 4;   // row group (8 rows)
    const float4* A4 = (const float4*)A;
    const float4* W4 = (const float4*)W;

    if (tid < BM) {
        rowsum[tid] = 0.f;
        s_cov[tid] = cov[n0 + tid];
    }

    for (int jt = 0; jt < NJT; ++jt) {
        __syncthreads();
        if (tid < BN) {
            int j = jt * BN + tid;
            s_cv[tid] = g_zconst[j];
            s_wc[tid] = wc[j];
            s_v[tid]  = vvec[j];
        }
        unsigned long long acc[4][8];
#pragma unroll
        for (int ii = 0; ii < 4; ++ii)
#pragma unroll
            for (int j = 0; j < 8; ++j) acc[ii][j] = 0ull;

        for (int kt = 0; kt < NKT; ++kt) {
            __syncthreads();
#pragma unroll
            for (int r = 0; r < 2; ++r) {
                int q = tid * 2 + r;            // 0..511
                int row = q >> 2, kq = q & 3;
                float4 va = A4[(size_t)(n0 + row) * (KDIM / 4) + kt * 4 + kq];
                As[kq * 4 + 0][row] = va.x; As[kq * 4 + 1][row] = va.y;
                As[kq * 4 + 2][row] = va.z; As[kq * 4 + 3][row] = va.w;
                float4 vb = W4[(size_t)(jt * BN + row) * (KDIM / 4) + kt * 4 + kq];
                Bs[kq * 4 + 0][row] = vb.x; Bs[kq * 4 + 1][row] = vb.y;
                Bs[kq * 4 + 2][row] = vb.z; Bs[kq * 4 + 3][row] = vb.w;
            }
            __syncthreads();
#pragma unroll
            for (int kk = 0; kk < BK; ++kk) {
                const ulonglong2* pa = (const ulonglong2*)&As[kk][ty * 8];
                ulonglong2 a01 = pa[0], a23 = pa[1];
                unsigned long long a2[4] = {a01.x, a01.y, a23.x, a23.y};
                const float4* pb = (const float4*)&Bs[kk][tx * 8];
                float4 b0 = pb[0], b1 = pb[1];
                unsigned long long bb[8];
                bb[0] = f32x2_dup(b0.x); bb[1] = f32x2_dup(b0.y);
                bb[2] = f32x2_dup(b0.z); bb[3] = f32x2_dup(b0.w);
                bb[4] = f32x2_dup(b1.x); bb[5] = f32x2_dup(b1.y);
                bb[6] = f32x2_dup(b1.z); bb[7] = f32x2_dup(b1.w);
#pragma unroll
                for (int ii = 0; ii < 4; ++ii)
#pragma unroll
                    for (int j = 0; j < 8; ++j)
                        f32x2_fma(acc[ii][j], a2[ii], bb[j]);
            }
        }
        // epilogue: reduce tanh over this 128-col tile into per-row partials
        float rp[8];
#pragma unroll
        for (int i = 0; i < 8; ++i) rp[i] = 0.f;
#pragma unroll
        for (int ii = 0; ii < 4; ++ii) {
            float c0 = s_cov[ty * 8 + 2 * ii];
            float c1 = s_cov[ty * 8 + 2 * ii + 1];
#pragma unroll
            for (int j = 0; j < 8; ++j) {
                float2 ch = f32x2_unpack(acc[ii][j]);
                int jc = tx * 8 + j;
                float base = s_cv[jc];
                float w    = s_wc[jc];
                float vv   = s_v[jc];
                rp[2 * ii]     += vv * tanhf(ch.x + base + c0 * w);
                rp[2 * ii + 1] += vv * tanhf(ch.y + base + c1 * w);
            }
        }
#pragma unroll
        for (int i = 0; i < 8; ++i) red[ty * 8 + i][tx] = rp[i];
        __syncthreads();
        if (tid < BM) {
            float s = 0.f;
#pragma unroll
            for (int t = 0; t < 16; ++t) s += red[tid][t];
            rowsum[tid] += s;
        }
    }
    __syncthreads();
    if (tid < BM) g_logits[n0 + tid] = rowsum[tid];
}

// ---------------- softmax (single CTA, deterministic) ----------------
// logit = g_logits[n] + vb; optional relu; prob = softmax; cov_out = cov + prob
__global__ void softmax_kernel(const float* __restrict__ vbp,
                               const float* __restrict__ cov,
                               float* __restrict__ prob_ext,
                               float* __restrict__ cov_out,
                               int do_relu) {
    __shared__ float shred[32];
    __shared__ float bval;
    int tid = threadIdx.x;  // 1024
    float vb = vbp[0];
    float lmax = -3.4e38f;
    for (int n = tid; n < NROWS; n += 1024) {
        float l = g_logits[n] + vb;
        if (do_relu) l = fmaxf(l, 0.f);
        g_logits[n] = l;
        lmax = fmaxf(lmax, l);
    }
#pragma unroll
    for (int o = 16; o; o >>= 1) lmax = fmaxf(lmax, __shfl_xor_sync(0xffffffffu, lmax, o));
    if ((tid & 31) == 0) shred[tid >> 5] = lmax;
    __syncthreads();
    if (tid < 32) {
        float v = shred[tid];
#pragma unroll
        for (int o = 16; o; o >>= 1) v = fmaxf(v, __shfl_xor_sync(0xffffffffu, v, o));
        if (tid == 0) bval = v;
    }
    __syncthreads();
    float m = bval;
    float lsum = 0.f;
    for (int n = tid; n < NROWS; n += 1024) lsum += expf(g_logits[n] - m);
#pragma unroll
    for (int o = 16; o; o >>= 1) lsum += __shfl_xor_sync(0xffffffffu, lsum, o);
    __syncthreads();
    if ((tid & 31) == 0) shred[tid >> 5] = lsum;
    __syncthreads();
    if (tid < 32) {
        float v = shred[tid];
#pragma unroll
        for (int o = 16; o; o >>= 1) v += __shfl_xor_sync(0xffffffffu, v, o);
        if (tid == 0) bval = v;
    }
    __syncthreads();
    float inv = 1.f / bval;
    float* prob = prob_ext ? prob_ext : g_attn;
    for (int n = tid; n < NROWS; n += 1024) {
        float p = expf(g_logits[n] - m) * inv;
        prob[n] = p;
        if (cov_out) cov_out[n] = cov[n] + p;
    }
}

// ---------------- weighted column sum: g_wenc = enc^T @ attn ----------------
__global__ void wsum_partial_kernel(const float* __restrict__ enc) {
    int col = blockIdx.x * 256 + threadIdx.x;  // gridDim.x = 4
    int n0 = blockIdx.y * 512;                 // gridDim.y = 64
    float s = 0.f;
#pragma unroll 4
    for (int n = n0; n < n0 + 512; ++n)
        s = fmaf(g_attn[n], enc[(size_t)n * KDIM + col], s);
    g_colpart[blockIdx.y * KDIM + col] = s;
}
__global__ void wsum_reduce_kernel() {
    int col = threadIdx.x;  // 1024
    float s = 0.f;
#pragma unroll
    for (int i = 0; i < 64; ++i) s += g_colpart[i * KDIM + col];
    g_wenc[col] = s;
}

// ---------------- h/c output copy ----------------
__global__ void copy_hc_kernel(float* __restrict__ oh, float* __restrict__ oc) {
    int i = blockIdx.x * blockDim.x + threadIdx.x;
    if (i < 2048) {
        oh[i] = g_h[i];
        oc[i] = g_c[i];
    }
}

// ---------------- launch ----------------
extern "C" void kernel_launch(void* const* d_in, const int* in_sizes, int n_in,
                              void* d_out, int out_size) {
    (void)in_sizes; (void)n_in;
    const float* inp   = (const float*)d_in[0];
    const float* h0    = (const float*)d_in[1];
    const float* c0    = (const float*)d_in[2];
    const float* enc   = (const float*)d_in[3];
    const float* cov_g = (const float*)d_in[4];
    const float* cov_p = (const float*)d_in[5];
    const float* Wih   = (const float*)d_in[6];
    const float* Whh   = (const float*)d_in[7];
    const float* bih   = (const float*)d_in[8];
    const float* bhh   = (const float*)d_in[9];
    const float* gw1   = (const float*)d_in[10];
    const float* gb1   = (const float*)d_in[11];
    const float* gw2   = (const float*)d_in[12];
    const float* gb2   = (const float*)d_in[13];
    const float* gwc   = (const float*)d_in[14];
    const float* gbc   = (const float*)d_in[15];
    const float* gv    = (const float*)d_in[16];
    const float* gvb   = (const float*)d_in[17];
    const float* pw1   = (const float*)d_in[18];
    const float* pb1   = (const float*)d_in[19];
    const float* pw2   = (const float*)d_in[20];
    const float* pb2   = (const float*)d_in[21];
    const float* pwc   = (const float*)d_in[22];
    const float* pbc   = (const float*)d_in[23];
    const float* pv    = (const float*)d_in[24];
    const float* pvb   = (const float*)d_in[25];

    float* out = (float*)d_out;
    const int FULL = 32768 + 2048 + 2048 + 32768 + 32768;  // 102400
    bool full = out_size >= FULL;
    float* out_h  = full ? out + 32768 : nullptr;
    float* out_c  = full ? out + 34816 : nullptr;
    float* out_cg = full ? out + 36864 : nullptr;
    float* out_cp = full ? out + 69632 : nullptr;

    // LSTM layer 0 (x = _input, h/c = h0[0]/c0[0])
    lstm_gates_kernel<<<512, 256>>>(Wih, Whh, bih, bhh, inp, h0);
    lstm_combine_kernel<<<1, 1024>>>(c0, 0);
    // LSTM layer 1 (x = g_h[0:1024], h/c = h0[1]/c0[1])
    lstm_gates_kernel<<<512, 256>>>(Wih + (size_t)4096 * 1024, Whh + (size_t)4096 * 1024,
                                    bih + 4096, bhh + 4096, nullptr, h0 + 1024);
    lstm_combine_kernel<<<1, 1024>>>(c0 + 1024, 1);

    // zconst_g = g_w2 @ lstm_out + g_b2 + g_b1 + g_bc
    matvec_kernel<<<128, 256>>>(gw2, gb2, gb1, gbc, /*x_sel=*/1, /*out_sel=*/0);

    // glimpse attention logits (fused GEMM + tanh + v-dot)
    score_gemm_kernel<<<256, 256>>>(enc, gw1, cov_g, gwc, gv);
    // attn = softmax(logits + vb); cov_g_new = cov_g + attn
    softmax_kernel<<<1, 1024>>>(gvb, cov_g, nullptr, out_cg, 0);

    // weighted_enc = enc^T @ attn  (context = g_w1 @ weighted_enc + g_b1)
    wsum_partial_kernel<<<dim3(4, 64), 256>>>(enc);
    wsum_reduce_kernel<<<1, 1024>>>();
    matvec_kernel<<<128, 256>>>(gw1, gb1, nullptr, nullptr, /*x_sel=*/2, /*out_sel=*/1);

    // zconst_p = p_w2 @ context + p_b2 + p_b1 + p_bc
    matvec_kernel<<<128, 256>>>(pw2, pb2, pb1, pbc, /*x_sel=*/3, /*out_sel=*/0);

    // pointer logits
    score_gemm_kernel<<<256, 256>>>(enc, pw1, cov_p, pwc, pv);
    // u = relu(logits + vb); cond_p = softmax(u) -> d_out; cov_p_new = cov_p + cond_p
    softmax_kernel<<<1, 1024>>>(pvb, cov_p, out, out_cp, 1);

    if (full) copy_hc_kernel<<<2, 1024>>>(out_h, out_c);
}